// round 12
// baseline (speedup 1.0000x reference)
#include <cuda_runtime.h>
#include <math.h>
#include <stdint.h>

#define B    8
#define N    4096
#define F    64
#define M    2048
#define KNB  32
#define H1   64
#define H2   128
#define R2   0.04f
#define CAP2 256

#define OUT_OFF   0
#define POSS_OFF  (B*M*H2)             // 2097152
#define NORMS_OFF (POSS_OFF + B*M*3)   // 2146304

// ---------------- scratch (no allocations allowed) ----------------
__device__ int    g_idx[B*M];
__device__ float  g_y[(size_t)B*N*H1];
__device__ int    g_nbr[B*M*KNB];
__device__ int    g_cnt[B*M];
__device__ float4 g_p4[B*N];

// ---------------- packed f32x2 helpers (sm_103a) ----------------
__device__ __forceinline__ uint64_t pk2(float lo, float hi) {
    uint64_t r;
    asm("mov.b64 %0, {%1, %2};" : "=l"(r)
        : "r"(__float_as_uint(lo)), "r"(__float_as_uint(hi)));
    return r;
}
__device__ __forceinline__ void upk2(float& lo, float& hi, uint64_t v) {
    unsigned a, b;
    asm("mov.b64 {%0, %1}, %2;" : "=r"(a), "=r"(b) : "l"(v));
    lo = __uint_as_float(a); hi = __uint_as_float(b);
}
__device__ __forceinline__ uint64_t add2(uint64_t a, uint64_t b) {
    uint64_t d; asm("add.rn.f32x2 %0, %1, %2;" : "=l"(d) : "l"(a), "l"(b)); return d;
}
__device__ __forceinline__ uint64_t mul2(uint64_t a, uint64_t b) {
    uint64_t d; asm("mul.rn.f32x2 %0, %1, %2;" : "=l"(d) : "l"(a), "l"(b)); return d;
}
__device__ __forceinline__ uint64_t fma2(uint64_t a, uint64_t b, uint64_t c) {
    uint64_t d; asm("fma.rn.f32x2 %0, %1, %2, %3;" : "=l"(d) : "l"(a), "l"(b), "l"(c)); return d;
}

// FROZEN exact-order |p|^2 (XLA uncontracted emission).
__device__ __forceinline__ float sum3sq_exact(float x, float y, float z)
{
    float a = __fmul_rn(x, x);
    float b = __fmul_rn(y, y);
    float c = __fmul_rn(z, z);
    return __fadd_rn(__fadd_rn(a, b), c);
}

// spread 3 bits to positions 0,3,6
__device__ __forceinline__ unsigned part3(unsigned v) {
    return (v & 1u) | ((v & 2u) << 2) | ((v & 4u) << 4);
}

// =============================================================
// FPS: 8x8x8 Morton counting sort; 256 threads, 16 pts/thread
// (tight bbox, cheap barrier). Skip test elides provable-no-op
// min() updates only -> dmin bit-identical to unpruned version.
// f32x2 distances bit-identical per lane to the frozen scalar
// sequence (x+(-l)==x-l, separate mul/add, XLA order).
// =============================================================
extern "C" __global__ void __launch_bounds__(256, 1)
fps_kernel(const float* __restrict__ pos)
{
    extern __shared__ float fsm[];
    float* spx  = fsm;               // N
    float* spy  = fsm + N;           // N
    float* spz  = fsm + 2*N;         // N
    int*   sidx = (int*)(fsm + 3*N); // N
    __shared__ int hist[512];
    __shared__ int offs[512];
    __shared__ unsigned s_wval[2][8];
    __shared__ unsigned s_wpay[2][8];

    const int b = blockIdx.x;
    const float* pb = pos + (size_t)b*N*3;
    const int t = threadIdx.x;
    const int lane = t & 31, wid = t >> 5;

    hist[t] = 0; hist[t + 256] = 0;
    __syncthreads();
    for (int i = t; i < N; i += 256) {
        float x = pb[3*i], y = pb[3*i+1], z = pb[3*i+2];
        unsigned cx = min(7, (int)(x*8.0f));
        unsigned cy = min(7, (int)(y*8.0f));
        unsigned cz = min(7, (int)(z*8.0f));
        unsigned cell = part3(cx) | (part3(cy) << 1) | (part3(cz) << 2);
        atomicAdd(&hist[cell], 1);
    }
    __syncthreads();
    if (t == 0) {
        int run = 0;
        for (int c = 0; c < 512; c++) { offs[c] = run; run += hist[c]; }
    }
    __syncthreads();
    for (int i = t; i < N; i += 256) {
        float x = pb[3*i], y = pb[3*i+1], z = pb[3*i+2];
        unsigned cx = min(7, (int)(x*8.0f));
        unsigned cy = min(7, (int)(y*8.0f));
        unsigned cz = min(7, (int)(z*8.0f));
        unsigned cell = part3(cx) | (part3(cy) << 1) | (part3(cz) << 2);
        int slot = atomicAdd(&offs[cell], 1);
        spx[slot] = x; spy[slot] = y; spz[slot] = z; sidx[slot] = i;
    }
    if (t == 0) g_idx[b*M] = 0;
    __syncthreads();

    const int base = 16*t;
    uint64_t PX[8], PY[8], PZ[8];
#pragma unroll
    for (int q = 0; q < 4; q++) {
        ulonglong2 xv = reinterpret_cast<const ulonglong2*>(spx)[4*t + q];
        ulonglong2 yv = reinterpret_cast<const ulonglong2*>(spy)[4*t + q];
        ulonglong2 zv = reinterpret_cast<const ulonglong2*>(spz)[4*t + q];
        PX[2*q] = xv.x; PX[2*q+1] = xv.y;
        PY[2*q] = yv.x; PY[2*q+1] = yv.y;
        PZ[2*q] = zv.x; PZ[2*q+1] = zv.y;
    }
    float dmin[16];
    unsigned pidx[16];
#pragma unroll
    for (int u = 0; u < 16; u++) {
        dmin[u] = 3.4e38f;
        pidx[u] = (((unsigned)sidx[base+u]) << 12) | (unsigned)(base + u);
    }
    float blx, bhx, bly, bhy, blz, bhz;
    {
        float a0, a1;
        upk2(a0, a1, PX[0]); blx = fminf(a0,a1); bhx = fmaxf(a0,a1);
        upk2(a0, a1, PY[0]); bly = fminf(a0,a1); bhy = fmaxf(a0,a1);
        upk2(a0, a1, PZ[0]); blz = fminf(a0,a1); bhz = fmaxf(a0,a1);
#pragma unroll
        for (int q = 1; q < 8; q++) {
            upk2(a0, a1, PX[q]); blx = fminf(blx, fminf(a0,a1)); bhx = fmaxf(bhx, fmaxf(a0,a1));
            upk2(a0, a1, PY[q]); bly = fminf(bly, fminf(a0,a1)); bhy = fmaxf(bhy, fmaxf(a0,a1));
            upk2(a0, a1, PZ[q]); blz = fminf(blz, fminf(a0,a1)); bhz = fmaxf(bhz, fmaxf(a0,a1));
        }
    }

    float lx = pb[0], ly = pb[1], lz = pb[2];
    float tmaxf = 3.4e38f;
    unsigned tbits = 0u, tpay = 0xffffffffu;
    int p = 0;

    for (int i = 1; i < M; i++) {
        float ddx = fmaxf(fmaxf(blx - lx, lx - bhx), 0.0f);
        float ddy = fmaxf(fmaxf(bly - ly, ly - bhy), 0.0f);
        float ddz = fmaxf(fmaxf(blz - lz, lz - bhz), 0.0f);
        float m2  = ddx*ddx + ddy*ddy + ddz*ddz;
        if (!(m2 * 0.999f > tmaxf)) {
            const uint64_t nlx = pk2(-lx, -lx);
            const uint64_t nly = pk2(-ly, -ly);
            const uint64_t nlz = pk2(-lz, -lz);
#pragma unroll
            for (int q = 0; q < 8; q++) {
                uint64_t dx = add2(PX[q], nlx);
                uint64_t dy = add2(PY[q], nly);
                uint64_t dz = add2(PZ[q], nlz);
                uint64_t s  = add2(add2(mul2(dx,dx), mul2(dy,dy)), mul2(dz,dz));
                float d0, d1; upk2(d0, d1, s);
                dmin[2*q]   = fminf(dmin[2*q],   d0);
                dmin[2*q+1] = fminf(dmin[2*q+1], d1);
            }
            float m0 = fmaxf(fmaxf(fmaxf(dmin[0],dmin[1]),fmaxf(dmin[2],dmin[3])),
                             fmaxf(fmaxf(dmin[4],dmin[5]),fmaxf(dmin[6],dmin[7])));
            float m1 = fmaxf(fmaxf(fmaxf(dmin[8],dmin[9]),fmaxf(dmin[10],dmin[11])),
                             fmaxf(fmaxf(dmin[12],dmin[13]),fmaxf(dmin[14],dmin[15])));
            float tm = fmaxf(m0, m1);
            unsigned pay = 0xffffffffu;
#pragma unroll
            for (int u = 0; u < 16; u++)
                if (dmin[u] == tm) pay = min(pay, pidx[u]);
            tmaxf = tm;
            tbits = __float_as_uint(tm);
            tpay  = pay;
        }
        unsigned wmax = __reduce_max_sync(0xffffffffu, tbits);
        unsigned pc   = (tbits == wmax) ? tpay : 0xffffffffu;
        unsigned wpay = __reduce_min_sync(0xffffffffu, pc);
        if (lane == 0) { s_wval[p][wid] = wmax; s_wpay[p][wid] = wpay; }
        __syncthreads();
        unsigned v   = (lane < 8) ? s_wval[p][lane] : 0u;
        unsigned pv  = (lane < 8) ? s_wpay[p][lane] : 0xffffffffu;
        unsigned gm  = __reduce_max_sync(0xffffffffu, v);
        unsigned gpc = (v == gm) ? pv : 0xffffffffu;
        unsigned gp  = __reduce_min_sync(0xffffffffu, gpc);
        int slot = (int)(gp & 0xfffu);
        lx = spx[slot]; ly = spy[slot]; lz = spz[slot];
        if (t == 0) g_idx[b*M + i] = (int)(gp >> 12);
        p ^= 1;
    }
}

// =============================================================
extern "C" __global__ void __launch_bounds__(256)
y_kernel(const float* __restrict__ x, const float* __restrict__ W1,
         const float* __restrict__ b1, int row0)
{
    __shared__ float W1s[64*64];
    __shared__ float xs[4][64];
    const int t = threadIdx.x;
    for (int i = t; i < 64*64; i += 256) W1s[i] = W1[i];
    const int g = t >> 6, c = t & 63;
    const int row = row0 + blockIdx.x*4 + g;
    xs[g][c] = x[(size_t)row*64 + c];
    __syncthreads();
    float acc = b1[c];
#pragma unroll 8
    for (int f = 0; f < 64; f++)
        acc = fmaf(xs[g][f], W1s[f*64 + c], acc);
    g_y[(size_t)row*64 + c] = acc;
}

extern "C" __global__ void p4_kernel(const float* __restrict__ pos)
{
    int i = blockIdx.x*256 + threadIdx.x;
    if (i >= B*N) return;
    float x = pos[3*i], y = pos[3*i+1], z = pos[3*i+2];
    g_p4[i] = make_float4(x, y, z, sum3sq_exact(x, y, z));
}

extern "C" __global__ void gather_kernel(const float* __restrict__ pos,
                                         const float* __restrict__ norm,
                                         float* __restrict__ outbuf)
{
    int i = blockIdx.x*256 + threadIdx.x;
    if (i >= B*M) return;
    int b = i / M;
    int j = g_idx[i];
    const float* p  = pos  + ((size_t)b*N + j)*3;
    const float* nr = norm + ((size_t)b*N + j)*3;
    outbuf[POSS_OFF  + i*3 + 0] = p[0];
    outbuf[POSS_OFF  + i*3 + 1] = p[1];
    outbuf[POSS_OFF  + i*3 + 2] = p[2];
    outbuf[NORMS_OFF + i*3 + 0] = nr[0];
    outbuf[NORMS_OFF + i*3 + 1] = nr[1];
    outbuf[NORMS_OFF + i*3 + 2] = nr[2];
}

// =============================================================
// neighbor selection (validated form). FROZEN d2 order.
// =============================================================
extern "C" __global__ void __launch_bounds__(256)
select_kernel(const float* __restrict__ outbuf)
{
    extern __shared__ float ssm[];
    float* cd = ssm;
    int*   ci = (int*)(cd + 32*CAP2);
    __shared__ int scnt[32];

    const int t = threadIdx.x;
    const int w = t >> 5, lane = t & 31;
    const int gid0 = blockIdx.x*32 + w*4;
    const int b = gid0 / M;

    if (t < 32) scnt[t] = 0;
    __syncthreads();

    float cx[4], cy[4], cz[4], si[4];
#pragma unroll
    for (int c = 0; c < 4; c++) {
        int gid = gid0 + c;
        cx[c] = outbuf[POSS_OFF + gid*3 + 0];
        cy[c] = outbuf[POSS_OFF + gid*3 + 1];
        cz[c] = outbuf[POSS_OFF + gid*3 + 2];
        si[c] = sum3sq_exact(cx[c], cy[c], cz[c]);
    }
    const float4* pp = g_p4 + (size_t)b*N;

#pragma unroll 2
    for (int p = lane; p < N; p += 32) {
        float4 P = __ldg(&pp[p]);
#pragma unroll
        for (int c = 0; c < 4; c++) {
            float dot = __fadd_rn(__fadd_rn(__fmul_rn(cx[c], P.x),
                                            __fmul_rn(cy[c], P.y)),
                                  __fmul_rn(cz[c], P.z));
            float d2 = __fsub_rn(__fadd_rn(si[c], P.w), __fmul_rn(2.0f, dot));
            if (d2 <= R2) {
                int wc = w*4 + c;
                int slot = atomicAdd(&scnt[wc], 1);
                if (slot < CAP2) { cd[wc*CAP2 + slot] = d2; ci[wc*CAP2 + slot] = p; }
            }
        }
    }
    __syncwarp();

#pragma unroll 1
    for (int c = 0; c < 4; c++) {
        const int wc = w*4 + c;
        const int gid = gid0 + c;
        int cnt = scnt[wc]; if (cnt > CAP2) cnt = CAP2;
        float* mycd = cd + wc*CAP2;
        int*   myci = ci + wc*CAP2;

        if (cnt <= KNB) {
            for (int s = lane; s < cnt; s += 32)
                g_nbr[gid*KNB + s] = myci[s];
            if (lane == 0) g_cnt[gid] = cnt;
        } else {
            for (int r = 0; r < KNB; r++) {
                float bvv = 3.4e38f; int bslot = -1;
                for (int s = lane; s < cnt; s += 32) {
                    float v = mycd[s];
                    if (v < bvv) { bvv = v; bslot = s; }
                }
                unsigned wmin = __reduce_min_sync(0xffffffffu, __float_as_uint(bvv));
                int pidx = (__float_as_uint(bvv) == wmin && bslot >= 0)
                             ? myci[bslot] : 0x7fffffff;
                int widx = (int)__reduce_min_sync(0xffffffffu, (unsigned)pidx);
                if (pidx == widx && bslot >= 0) mycd[bslot] = 3.4e38f;
                if (lane == 0) g_nbr[gid*KNB + r] = widx;
                __syncwarp();
            }
            if (lane == 0) g_cnt[gid] = KNB;
        }
    }
}

// =============================================================
// fused PPF + layer1-residual + layer2 + masked max.
// 256 threads; W2 pre-duplicated as (w,w) u64 pairs in dynamic
// smem (no per-f packing movs); h1t stride 36 -> LDS128 h loads
// (warp-uniform broadcast). Per-(k,c) math order identical to
// the validated kernel (same fma2 chain, same max/b2/relu order).
// =============================================================
__device__ __forceinline__ float get_angle(float ax, float ay, float az,
                                           float bx, float by, float bz)
{
    float cxv = ay*bz - az*by;
    float cyv = az*bx - ax*bz;
    float czv = ax*by - ay*bx;
    float cn  = sqrtf(cxv*cxv + cyv*cyv + czv*czv);
    float d   = ax*bx + ay*by + az*bz;
    if (cn == 0.0f && d == 0.0f) d = 1.0f;
    return atan2f(cn, d);
}

#define MLP_DYN ((64*128)*8 + 64*36*4 + 8*128*4)   // W2p + h1t + pm = 78848 B

extern "C" __global__ void __launch_bounds__(256)
mlp_kernel(const float* __restrict__ pos, const float* __restrict__ norm,
           const float* __restrict__ W1, const float* __restrict__ W2,
           const float* __restrict__ b2, float* __restrict__ outbuf)
{
    extern __shared__ uint64_t dynsm[];
    uint64_t* W2p = dynsm;                       // 64*128 u64 pairs
    float*    h1t = (float*)(W2p + 64*128);      // 64*36
    float*    pm  = h1t + 64*36;                 // 8*128
    __shared__ float b2s[128];
    __shared__ float W1bs[256];
    __shared__ int   snbr[32];
    __shared__ int   scnt_s;
    __shared__ float scen[6];

    const int t = threadIdx.x;
    for (int i = t; i < 64*128; i += 256) {
        float wv = W2[i];
        W2p[i] = pk2(wv, wv);
    }
    b2s[t & 127] = b2[t & 127];
    W1bs[t] = W1[64*64 + t];

    for (int cblk = 0; cblk < 8; cblk++) {
        const int gid = blockIdx.x*8 + cblk;
        const int b = gid / M;
        __syncthreads();   // protect smem reuse across centers
        if (t < 32) snbr[t] = g_nbr[gid*KNB + t];
        if (t == 32) scnt_s = g_cnt[gid];
        if (t >= 40 && t < 43) scen[t-40]     = outbuf[POSS_OFF  + gid*3 + (t-40)];
        if (t >= 43 && t < 46) scen[3 + t-43] = outbuf[NORMS_OFF + gid*3 + (t-43)];
        __syncthreads();
        const int cnt = scnt_s;

        // ---- edge phase (identical math; only t<128 participate) ----
        if (t < 128) {
            const int k = t >> 2, q = t & 3;
            const int j = (k < cnt) ? snbr[k] : 0;
            const float* pj = pos  + ((size_t)b*N + j)*3;
            const float* nj = norm + ((size_t)b*N + j)*3;
            float px = pj[0], py = pj[1], pz = pj[2];
            float nx = nj[0], ny = nj[1], nz = nj[2];
            float cxp = scen[0], cyp = scen[1], czp = scen[2];
            float nix = scen[3], niy = scen[4], niz = scen[5];
            float dx = px - cxp, dy = py - cyp, dz = pz - czp;
            float f0 = sqrtf(dx*dx + dy*dy + dz*dz);
            float f1 = get_angle(nix, niy, niz, dx, dy, dz);
            float f2 = get_angle(nx,  ny,  nz,  dx, dy, dz);
            float f3 = get_angle(nix, niy, niz, nx, ny, nz);
            const float* yrow = g_y + ((size_t)b*N + j)*64 + q*16;
#pragma unroll
            for (int u = 0; u < 16; u++) {
                int f = q*16 + u;
                float v = yrow[u];
                v = fmaf(f0, W1bs[f],       v);
                v = fmaf(f1, W1bs[64  + f], v);
                v = fmaf(f2, W1bs[128 + f], v);
                v = fmaf(f3, W1bs[192 + f], v);
                h1t[f*36 + k] = fmaxf(v, 0.0f);
            }
        }
        __syncthreads();

        // ---- layer 2 (FFMA2): 8 kq-groups x 4 k; pre-packed W2 ----
        {
            const int kq = t >> 5, cg = t & 31;
            uint64_t accp[2][4];
#pragma unroll
            for (int ep = 0; ep < 2; ep++)
#pragma unroll
                for (int c = 0; c < 4; c++) accp[ep][c] = 0ull;

#pragma unroll 4
            for (int f = 0; f < 64; f++) {
                ulonglong2 hv = *reinterpret_cast<const ulonglong2*>(&h1t[f*36 + kq*4]);
                ulonglong2 wa = *reinterpret_cast<const ulonglong2*>(&W2p[f*128 + cg*4]);
                ulonglong2 wb = *reinterpret_cast<const ulonglong2*>(&W2p[f*128 + cg*4 + 2]);
                accp[0][0] = fma2(hv.x, wa.x, accp[0][0]);
                accp[0][1] = fma2(hv.x, wa.y, accp[0][1]);
                accp[0][2] = fma2(hv.x, wb.x, accp[0][2]);
                accp[0][3] = fma2(hv.x, wb.y, accp[0][3]);
                accp[1][0] = fma2(hv.y, wa.x, accp[1][0]);
                accp[1][1] = fma2(hv.y, wa.y, accp[1][1]);
                accp[1][2] = fma2(hv.y, wb.x, accp[1][2]);
                accp[1][3] = fma2(hv.y, wb.y, accp[1][3]);
            }
            float v0 = -3.4e38f, v1 = -3.4e38f, v2 = -3.4e38f, v3 = -3.4e38f;
#pragma unroll
            for (int ep = 0; ep < 2; ep++) {
                const int e0 = kq*4 + 2*ep;
                float a, bb;
                upk2(a, bb, accp[ep][0]);
                if (e0     < cnt) v0 = fmaxf(v0, a);
                if (e0 + 1 < cnt) v0 = fmaxf(v0, bb);
                upk2(a, bb, accp[ep][1]);
                if (e0     < cnt) v1 = fmaxf(v1, a);
                if (e0 + 1 < cnt) v1 = fmaxf(v1, bb);
                upk2(a, bb, accp[ep][2]);
                if (e0     < cnt) v2 = fmaxf(v2, a);
                if (e0 + 1 < cnt) v2 = fmaxf(v2, bb);
                upk2(a, bb, accp[ep][3]);
                if (e0     < cnt) v3 = fmaxf(v3, a);
                if (e0 + 1 < cnt) v3 = fmaxf(v3, bb);
            }
            *reinterpret_cast<float4*>(&pm[kq*128 + cg*4]) =
                make_float4(v0, v1, v2, v3);
        }
        __syncthreads();

        // ---- combine 8 k-groups, add b2, relu, store ----
        if (t < 128) {
            float v = pm[t];
#pragma unroll
            for (int g = 1; g < 8; g++) v = fmaxf(v, pm[g*128 + t]);
            float r = fmaxf(v + b2s[t], 0.0f);
            outbuf[(size_t)gid*128 + t] = r;
        }
    }
}

// =============================================================
extern "C" void kernel_launch(void* const* d_in, const int* in_sizes, int n_in,
                              void* d_out, int out_size)
{
    const float* x    = (const float*)d_in[0];
    const float* pos  = (const float*)d_in[1];
    const float* norm = (const float*)d_in[2];
    const float* W1   = (const float*)d_in[3];
    const float* b1   = (const float*)d_in[4];
    const float* W2   = (const float*)d_in[5];
    const float* b2   = (const float*)d_in[6];
    float* out = (float*)d_out;

    (void)in_sizes; (void)n_in; (void)out_size;

    cudaFuncSetAttribute(fps_kernel,
        cudaFuncAttributeMaxDynamicSharedMemorySize, 4*N*4);
    cudaFuncSetAttribute(select_kernel,
        cudaFuncAttributeMaxDynamicSharedMemorySize, 32*CAP2*8);
    cudaFuncSetAttribute(mlp_kernel,
        cudaFuncAttributeMaxDynamicSharedMemorySize, MLP_DYN);

    // launch order chosen so fps_kernel is capture index 3 (ncu)
    y_kernel<<<B*N/8, 256>>>(x, W1, b1, 0);
    y_kernel<<<B*N/8, 256>>>(x, W1, b1, B*N/2);
    p4_kernel<<<(B*N + 255)/256, 256>>>(pos);
    fps_kernel<<<B, 256, 4*N*4>>>(pos);
    gather_kernel<<<(B*M + 255)/256, 256>>>(pos, norm, out);
    select_kernel<<<B*M/32, 256, 32*CAP2*8>>>(out);
    mlp_kernel<<<B*M/8, 256, MLP_DYN>>>(pos, norm, W1, W2, b2, out);
}